// round 5
// baseline (speedup 1.0000x reference)
#include <cuda_runtime.h>
#include <cuda_bf16.h>
#include <cstdint>

#define E_MAX 100096
#define IN_F  256
#define HID   128

// scratch (device globals = allowed scratch)
__device__ float g_t[(size_t)E_MAX * HID];
__device__ __nv_bfloat16 g_wt_hi[HID * IN_F];   // W transposed [n][k], hi part
__device__ __nv_bfloat16 g_wt_lo[HID * IN_F];   // lo part

__device__ __forceinline__ uint32_t smem_u32(const void* p) {
    uint32_t a;
    asm("{ .reg .u64 t; cvta.to.shared.u64 t, %1; cvt.u32.u64 %0, t; }" : "=r"(a) : "l"(p));
    return a;
}
__device__ __forceinline__ void ldsm_x4(uint32_t& r0, uint32_t& r1, uint32_t& r2,
                                        uint32_t& r3, uint32_t addr) {
    asm volatile("ldmatrix.sync.aligned.m8n8.x4.shared.b16 {%0,%1,%2,%3}, [%4];"
                 : "=r"(r0), "=r"(r1), "=r"(r2), "=r"(r3) : "r"(addr));
}
__device__ __forceinline__ void mma16816(float* c, uint32_t a0, uint32_t a1,
                                         uint32_t a2, uint32_t a3,
                                         uint32_t b0, uint32_t b1) {
    asm volatile(
        "mma.sync.aligned.m16n8k16.row.col.f32.bf16.bf16.f32 "
        "{%0,%1,%2,%3}, {%4,%5,%6,%7}, {%8,%9}, {%0,%1,%2,%3};"
        : "+f"(c[0]), "+f"(c[1]), "+f"(c[2]), "+f"(c[3])
        : "r"(a0), "r"(a1), "r"(a2), "r"(a3), "r"(b0), "r"(b1));
}

// =====================================================================
// W transpose + bf16 hi/lo split (one-shot tiny kernel)
// =====================================================================
__global__ void wconv_kernel(const float* __restrict__ W) {
    int i = blockIdx.x * 256 + threadIdx.x;
    if (i >= IN_F * HID) return;
    int k = i >> 7, n = i & 127;
    float v = W[i];
    __nv_bfloat16 h = __float2bfloat16(v);
    float lo = v - __bfloat162float(h);
    g_wt_hi[n * IN_F + k] = h;
    g_wt_lo[n * IN_F + k] = __float2bfloat16(lo);
}

// =====================================================================
// t = X @ W + b : bf16 3-term split on mma.sync, fp32 accum
// CTA = 128x128, 8 warps (4m x 2n), BK=32, DOUBLE-BUFFERED smem,
// one __syncthreads per chunk; staging of k+1 overlaps compute of k.
// =====================================================================
#define BK 32
#define STR 40                  // smem row stride (bf16): 80 B, conflict-free ldsm
#define BUF_ELEMS (128 * STR)   // 5120 bf16 = 10240 B per matrix per stage
#define SMEM_BYTES (8 * BUF_ELEMS * 2)   // 81920 B

__device__ __forceinline__ void stage_chunk(
    const float4* __restrict__ X4,
    const uint4* __restrict__ bh4, const uint4* __restrict__ bl4,
    __nv_bfloat16* sAh, __nv_bfloat16* sAl,
    __nv_bfloat16* sBh, __nv_bfloat16* sBl,
    int tid, int rowBase, int kc, int E)
{
    // ---- A: 128 rows x 32 k fp32 -> bf16 hi/lo ----
#pragma unroll
    for (int it = 0; it < 4; ++it) {
        int i = it * 256 + tid;       // 1024 float4
        int r = i >> 3, f = i & 7;
        int grow = rowBase + r;
        if (grow >= E) grow = E - 1;
        float4 v = X4[grow * (IN_F / 4) + kc * 8 + f];
        __nv_bfloat16 h0 = __float2bfloat16(v.x);
        __nv_bfloat16 h1 = __float2bfloat16(v.y);
        __nv_bfloat16 h2 = __float2bfloat16(v.z);
        __nv_bfloat16 h3 = __float2bfloat16(v.w);
        __nv_bfloat16 l0 = __float2bfloat16(v.x - __bfloat162float(h0));
        __nv_bfloat16 l1 = __float2bfloat16(v.y - __bfloat162float(h1));
        __nv_bfloat16 l2 = __float2bfloat16(v.z - __bfloat162float(h2));
        __nv_bfloat16 l3 = __float2bfloat16(v.w - __bfloat162float(h3));
        uint2 hp, lp;
        hp.x = ((uint32_t)__bfloat16_as_ushort(h1) << 16) | __bfloat16_as_ushort(h0);
        hp.y = ((uint32_t)__bfloat16_as_ushort(h3) << 16) | __bfloat16_as_ushort(h2);
        lp.x = ((uint32_t)__bfloat16_as_ushort(l1) << 16) | __bfloat16_as_ushort(l0);
        lp.y = ((uint32_t)__bfloat16_as_ushort(l3) << 16) | __bfloat16_as_ushort(l2);
        *(uint2*)(sAh + r * STR + f * 4) = hp;
        *(uint2*)(sAl + r * STR + f * 4) = lp;
    }
    // ---- B: 128 n x 32 k, pre-split bf16 hi/lo ----
#pragma unroll
    for (int it = 0; it < 2; ++it) {
        int i = it * 256 + tid;       // 512 uint4 per matrix
        int n = i >> 2, q = i & 3;
        *(uint4*)(sBh + n * STR + q * 8) = bh4[n * 32 + kc * 4 + q];
        *(uint4*)(sBl + n * STR + q * 8) = bl4[n * 32 + kc * 4 + q];
    }
}

__global__ __launch_bounds__(256, 2)
void gemm_mma_kernel(const float* __restrict__ X,
                     const float* __restrict__ bias,
                     int E) {
    extern __shared__ __nv_bfloat16 dsm[];

    const int tid  = threadIdx.x;
    const int wid  = tid >> 5;
    const int lane = tid & 31;
    const int wm   = wid & 3;
    const int wn   = wid >> 2;
    const int rowBase = blockIdx.x * 128;

    float acc[2][8][4];
#pragma unroll
    for (int mi = 0; mi < 2; ++mi)
#pragma unroll
        for (int ni = 0; ni < 8; ++ni)
#pragma unroll
            for (int q = 0; q < 4; ++q) acc[mi][ni][q] = 0.f;

    const float4* X4  = (const float4*)X;
    const uint4*  bh4 = (const uint4*)g_wt_hi;
    const uint4*  bl4 = (const uint4*)g_wt_lo;

    // buffer s (0/1), matrix m: 0=Ah 1=Al 2=Bh 3=Bl
    __nv_bfloat16* buf[2][4];
#pragma unroll
    for (int s = 0; s < 2; ++s)
#pragma unroll
        for (int m = 0; m < 4; ++m) buf[s][m] = dsm + (s * 4 + m) * BUF_ELEMS;

    const uint32_t dsm_b = smem_u32(dsm);

    const int lrow = (lane & 7) + ((lane >> 3) & 1) * 8;
    const int lkof = ((lane >> 4) & 1) * 8;

    // prologue: stage chunk 0 into buffer 0
    stage_chunk(X4, bh4, bl4, buf[0][0], buf[0][1], buf[0][2], buf[0][3],
                tid, rowBase, 0, E);
    __syncthreads();

    for (int kc = 0; kc < IN_F / BK; ++kc) {
        const int cur = kc & 1;
        // stage next chunk into the other buffer (overlaps with compute below;
        // LDGs issue first, MMA latency hides them)
        if (kc + 1 < IN_F / BK) {
            stage_chunk(X4, bh4, bl4,
                        buf[cur ^ 1][0], buf[cur ^ 1][1], buf[cur ^ 1][2], buf[cur ^ 1][3],
                        tid, rowBase, kc + 1, E);
        }

        const uint32_t ah_b = dsm_b + (uint32_t)((cur * 4 + 0) * BUF_ELEMS) * 2;
        const uint32_t al_b = dsm_b + (uint32_t)((cur * 4 + 1) * BUF_ELEMS) * 2;
        const uint32_t bh_b = dsm_b + (uint32_t)((cur * 4 + 2) * BUF_ELEMS) * 2;
        const uint32_t bl_b = dsm_b + (uint32_t)((cur * 4 + 3) * BUF_ELEMS) * 2;

#pragma unroll
        for (int ks = 0; ks < 2; ++ks) {
            const int kk = ks * 16;
            uint32_t af[2][4], bf[4][4];

            // pass 0: Ah x Bh
#pragma unroll
            for (int mi = 0; mi < 2; ++mi)
                ldsm_x4(af[mi][0], af[mi][1], af[mi][2], af[mi][3],
                        ah_b + ((wm * 32 + mi * 16 + lrow) * STR + kk + lkof) * 2);
#pragma unroll
            for (int bi = 0; bi < 4; ++bi)
                ldsm_x4(bf[bi][0], bf[bi][1], bf[bi][2], bf[bi][3],
                        bh_b + ((wn * 64 + bi * 16 + lrow) * STR + kk + lkof) * 2);
#pragma unroll
            for (int mi = 0; mi < 2; ++mi)
#pragma unroll
                for (int bi = 0; bi < 4; ++bi) {
                    mma16816(acc[mi][bi * 2 + 0], af[mi][0], af[mi][1], af[mi][2], af[mi][3],
                             bf[bi][0], bf[bi][2]);
                    mma16816(acc[mi][bi * 2 + 1], af[mi][0], af[mi][1], af[mi][2], af[mi][3],
                             bf[bi][1], bf[bi][3]);
                }

            // pass 1: Al x Bh (B fragments resident)
#pragma unroll
            for (int mi = 0; mi < 2; ++mi)
                ldsm_x4(af[mi][0], af[mi][1], af[mi][2], af[mi][3],
                        al_b + ((wm * 32 + mi * 16 + lrow) * STR + kk + lkof) * 2);
#pragma unroll
            for (int mi = 0; mi < 2; ++mi)
#pragma unroll
                for (int bi = 0; bi < 4; ++bi) {
                    mma16816(acc[mi][bi * 2 + 0], af[mi][0], af[mi][1], af[mi][2], af[mi][3],
                             bf[bi][0], bf[bi][2]);
                    mma16816(acc[mi][bi * 2 + 1], af[mi][0], af[mi][1], af[mi][2], af[mi][3],
                             bf[bi][1], bf[bi][3]);
                }

            // pass 2: Ah x Bl
#pragma unroll
            for (int mi = 0; mi < 2; ++mi)
                ldsm_x4(af[mi][0], af[mi][1], af[mi][2], af[mi][3],
                        ah_b + ((wm * 32 + mi * 16 + lrow) * STR + kk + lkof) * 2);
#pragma unroll
            for (int bi = 0; bi < 4; ++bi)
                ldsm_x4(bf[bi][0], bf[bi][1], bf[bi][2], bf[bi][3],
                        bl_b + ((wn * 64 + bi * 16 + lrow) * STR + kk + lkof) * 2);
#pragma unroll
            for (int mi = 0; mi < 2; ++mi)
#pragma unroll
                for (int bi = 0; bi < 4; ++bi) {
                    mma16816(acc[mi][bi * 2 + 0], af[mi][0], af[mi][1], af[mi][2], af[mi][3],
                             bf[bi][0], bf[bi][2]);
                    mma16816(acc[mi][bi * 2 + 1], af[mi][0], af[mi][1], af[mi][2], af[mi][3],
                             bf[bi][1], bf[bi][3]);
                }
        }
        __syncthreads();
    }

    // ---- epilogue: + bias, store t ----
    const int gid = lane >> 2;
    const int cid = (lane & 3) * 2;
#pragma unroll
    for (int mi = 0; mi < 2; ++mi) {
        int row0 = rowBase + wm * 32 + mi * 16 + gid;
#pragma unroll
        for (int ni = 0; ni < 8; ++ni) {
            int col = wn * 64 + ni * 8 + cid;
            float b0 = __ldg(bias + col), b1 = __ldg(bias + col + 1);
            if (row0 < E) {
                float2 o = {acc[mi][ni][0] + b0, acc[mi][ni][1] + b1};
                *(float2*)(g_t + (size_t)row0 * HID + col) = o;
            }
            if (row0 + 8 < E) {
                float2 o = {acc[mi][ni][2] + b0, acc[mi][ni][3] + b1};
                *(float2*)(g_t + (size_t)(row0 + 8) * HID + col) = o;
            }
        }
    }
}

// =====================================================================
// out[i] = t[i] + sum_k t[nbr[i][k]]   (L2-bound; unchanged)
// =====================================================================
__global__ __launch_bounds__(256)
void gather_sum_kernel(const int* __restrict__ nbr,
                       float* __restrict__ out,
                       int E) {
    int gtid = blockIdx.x * blockDim.x + threadIdx.x;
    int e    = gtid >> 5;
    int lane = threadIdx.x & 31;
    if (e >= E) return;

    const float4* T4 = (const float4*)g_t;

    int j = 0;
    if (lane < 16) j = nbr[e * 16 + lane];

    float4 acc = T4[e * 32 + lane];

    float4 v[16];
#pragma unroll
    for (int k = 0; k < 16; ++k) {
        int n = __shfl_sync(0xffffffffu, j, k);
        v[k] = T4[n * 32 + lane];
    }
#pragma unroll
    for (int k = 0; k < 16; ++k) {
        acc.x += v[k].x;
        acc.y += v[k].y;
        acc.z += v[k].z;
        acc.w += v[k].w;
    }
    ((float4*)out)[e * 32 + lane] = acc;
}

extern "C" void kernel_launch(void* const* d_in, const int* in_sizes, int n_in,
                              void* d_out, int out_size) {
    const float* X   = (const float*)d_in[0];   // edge_feats [E, 256]
    const int*   nbr = (const int*)  d_in[1];   // neighbors  [E, 16]
    const float* W   = (const float*)d_in[2];   // W          [256, 128]
    const float* b   = (const float*)d_in[3];   // b          [128]
    float* out = (float*)d_out;                 // [E, 128]

    int E = in_sizes[0] / IN_F;

    // not a stream op; safe under graph capture, called unconditionally
    cudaFuncSetAttribute(gemm_mma_kernel,
                         cudaFuncAttributeMaxDynamicSharedMemorySize, SMEM_BYTES);

    wconv_kernel<<<(IN_F * HID + 255) / 256, 256>>>(W);

    int gblocks = (E + 127) / 128;
    gemm_mma_kernel<<<gblocks, 256, SMEM_BYTES>>>(X, b, E);

    long long threads = (long long)E * 32;      // one warp per edge
    int blocks2 = (int)((threads + 255) / 256);
    gather_sum_kernel<<<blocks2, 256>>>(nbr, out, E);
}

// round 6
// speedup vs baseline: 1.1183x; 1.1183x over previous
#include <cuda_runtime.h>
#include <cuda_bf16.h>
#include <cstdint>

#define E_MAX 100096
#define IN_F  256
#define HID   128

// scratch (device globals = allowed scratch)
__device__ float g_t[(size_t)E_MAX * HID];
__device__ __nv_bfloat16 g_wt_hi[HID * IN_F];   // W transposed [n][k], hi part
__device__ __nv_bfloat16 g_wt_lo[HID * IN_F];   // lo part

__device__ __forceinline__ uint32_t smem_u32(const void* p) {
    uint32_t a;
    asm("{ .reg .u64 t; cvta.to.shared.u64 t, %1; cvt.u32.u64 %0, t; }" : "=r"(a) : "l"(p));
    return a;
}
__device__ __forceinline__ void ldsm_x4(uint32_t& r0, uint32_t& r1, uint32_t& r2,
                                        uint32_t& r3, uint32_t addr) {
    asm volatile("ldmatrix.sync.aligned.m8n8.x4.shared.b16 {%0,%1,%2,%3}, [%4];"
                 : "=r"(r0), "=r"(r1), "=r"(r2), "=r"(r3) : "r"(addr));
}
__device__ __forceinline__ void mma16816(float* c, uint32_t a0, uint32_t a1,
                                         uint32_t a2, uint32_t a3,
                                         uint32_t b0, uint32_t b1) {
    asm volatile(
        "mma.sync.aligned.m16n8k16.row.col.f32.bf16.bf16.f32 "
        "{%0,%1,%2,%3}, {%4,%5,%6,%7}, {%8,%9}, {%0,%1,%2,%3};"
        : "+f"(c[0]), "+f"(c[1]), "+f"(c[2]), "+f"(c[3])
        : "r"(a0), "r"(a1), "r"(a2), "r"(a3), "r"(b0), "r"(b1));
}
__device__ __forceinline__ void cp_async16(uint32_t dst, const void* src) {
    asm volatile("cp.async.cg.shared.global [%0], [%1], 16;" :: "r"(dst), "l"(src));
}
#define CP_COMMIT() asm volatile("cp.async.commit_group;" ::: "memory")
#define CP_WAIT0()  asm volatile("cp.async.wait_group 0;" ::: "memory")

// =====================================================================
// W transpose + bf16 hi/lo split (one-shot tiny kernel)
// =====================================================================
__global__ void wconv_kernel(const float* __restrict__ W) {
    int i = blockIdx.x * 256 + threadIdx.x;
    if (i >= IN_F * HID) return;
    int k = i >> 7, n = i & 127;
    float v = W[i];
    __nv_bfloat16 h = __float2bfloat16(v);
    float lo = v - __bfloat162float(h);
    g_wt_hi[n * IN_F + k] = h;
    g_wt_lo[n * IN_F + k] = __float2bfloat16(lo);
}

// =====================================================================
// t = X @ W + b : bf16 3-term split on mma.sync, fp32 accum
// CTA = 128x128, 8 warps (4m x 2n), BK=32.
// cp.async pipeline: X fp32 + B bf16 double-buffered async copies;
// A convert reads smem; single-buffered A bf16 tiles; regs same as R3.
// =====================================================================
#define BK 32
#define STR 40                       // smem row stride (bf16): 80 B
#define TILE_B (128 * STR * 2)       // 10240 B per matrix tile

// smem byte offsets
#define SM_XF 0                      // X fp32 staging: 2 x 16384
#define SM_AH 32768                  // A hi bf16 tile (single)
#define SM_AL 43008                  // A lo bf16 tile (single)
#define SM_B  53248                  // B tiles: [buf][hi|lo], 2 x 2 x 10240
#define SMEM_BYTES (53248 + 40960)   // 94208

__device__ __forceinline__ void prefetch_chunk(
    uint32_t smb, int buf,
    const float4* __restrict__ X4,
    const uint4* __restrict__ bh4, const uint4* __restrict__ bl4,
    int tid, int rowBase, int kc, int E)
{
    uint32_t xdst = smb + SM_XF + buf * 16384;
#pragma unroll
    for (int it = 0; it < 4; ++it) {
        int i = it * 256 + tid;          // 1024 float4  (i == r*8+f)
        int r = i >> 3, f = i & 7;
        int grow = rowBase + r;
        if (grow >= E) grow = E - 1;
        cp_async16(xdst + i * 16, X4 + grow * (IN_F / 4) + kc * 8 + f);
    }
    uint32_t bdst = smb + SM_B + buf * (2 * TILE_B);
#pragma unroll
    for (int it = 0; it < 2; ++it) {
        int i = it * 256 + tid;          // 512 uint4 per matrix
        int n = i >> 2, q = i & 3;
        uint32_t off = (uint32_t)(n * STR + q * 8) * 2;    // 16B-aligned
        cp_async16(bdst + off,          bh4 + n * 32 + kc * 4 + q);
        cp_async16(bdst + TILE_B + off, bl4 + n * 32 + kc * 4 + q);
    }
    CP_COMMIT();
}

__device__ __forceinline__ void convert_A(char* smem, int buf, int tid) {
    const float4* xf = (const float4*)(smem + SM_XF + buf * 16384);
    __nv_bfloat16* sAh = (__nv_bfloat16*)(smem + SM_AH);
    __nv_bfloat16* sAl = (__nv_bfloat16*)(smem + SM_AL);
#pragma unroll
    for (int it = 0; it < 4; ++it) {
        int i = it * 256 + tid;
        int r = i >> 3, f = i & 7;
        float4 v = xf[i];
        __nv_bfloat16 h0 = __float2bfloat16(v.x);
        __nv_bfloat16 h1 = __float2bfloat16(v.y);
        __nv_bfloat16 h2 = __float2bfloat16(v.z);
        __nv_bfloat16 h3 = __float2bfloat16(v.w);
        __nv_bfloat16 l0 = __float2bfloat16(v.x - __bfloat162float(h0));
        __nv_bfloat16 l1 = __float2bfloat16(v.y - __bfloat162float(h1));
        __nv_bfloat16 l2 = __float2bfloat16(v.z - __bfloat162float(h2));
        __nv_bfloat16 l3 = __float2bfloat16(v.w - __bfloat162float(h3));
        uint2 hp, lp;
        hp.x = ((uint32_t)__bfloat16_as_ushort(h1) << 16) | __bfloat16_as_ushort(h0);
        hp.y = ((uint32_t)__bfloat16_as_ushort(h3) << 16) | __bfloat16_as_ushort(h2);
        lp.x = ((uint32_t)__bfloat16_as_ushort(l1) << 16) | __bfloat16_as_ushort(l0);
        lp.y = ((uint32_t)__bfloat16_as_ushort(l3) << 16) | __bfloat16_as_ushort(l2);
        *(uint2*)(sAh + r * STR + f * 4) = hp;
        *(uint2*)(sAl + r * STR + f * 4) = lp;
    }
}

__global__ __launch_bounds__(256, 2)
void gemm_mma_kernel(const float* __restrict__ X,
                     const float* __restrict__ bias,
                     int E) {
    extern __shared__ char smem[];

    const int tid  = threadIdx.x;
    const int wid  = tid >> 5;
    const int lane = tid & 31;
    const int wm   = wid & 3;
    const int wn   = wid >> 2;
    const int rowBase = blockIdx.x * 128;

    float acc[2][8][4];
#pragma unroll
    for (int mi = 0; mi < 2; ++mi)
#pragma unroll
        for (int ni = 0; ni < 8; ++ni)
#pragma unroll
            for (int q = 0; q < 4; ++q) acc[mi][ni][q] = 0.f;

    const float4* X4  = (const float4*)X;
    const uint4*  bh4 = (const uint4*)g_wt_hi;
    const uint4*  bl4 = (const uint4*)g_wt_lo;

    const uint32_t smb = smem_u32(smem);

    const int lrow = (lane & 7) + ((lane >> 3) & 1) * 8;
    const int lkof = ((lane >> 4) & 1) * 8;

    // prologue: async-stage chunk 0 into buffer 0
    prefetch_chunk(smb, 0, X4, bh4, bl4, tid, rowBase, 0, E);

    for (int kc = 0; kc < IN_F / BK; ++kc) {
        const int buf = kc & 1;

        CP_WAIT0();
        __syncthreads();           // data visible to all; A tiles free (prev compute done)

        convert_A(smem, buf, tid); // smem->smem, L1 latency only

        if (kc + 1 < IN_F / BK)    // prefetch next chunk; hidden behind compute below
            prefetch_chunk(smb, buf ^ 1, X4, bh4, bl4, tid, rowBase, kc + 1, E);

        __syncthreads();           // A tiles ready for compute

        const uint32_t ah_b = smb + SM_AH;
        const uint32_t al_b = smb + SM_AL;
        const uint32_t bh_b = smb + SM_B + (uint32_t)buf * (2 * TILE_B);
        const uint32_t bl_b = bh_b + TILE_B;

#pragma unroll
        for (int ks = 0; ks < 2; ++ks) {
            const int kk = ks * 16;
            uint32_t af[2][4], bf[4][4];

            // pass 0: Ah x Bh
#pragma unroll
            for (int mi = 0; mi < 2; ++mi)
                ldsm_x4(af[mi][0], af[mi][1], af[mi][2], af[mi][3],
                        ah_b + ((wm * 32 + mi * 16 + lrow) * STR + kk + lkof) * 2);
#pragma unroll
            for (int bi = 0; bi < 4; ++bi)
                ldsm_x4(bf[bi][0], bf[bi][1], bf[bi][2], bf[bi][3],
                        bh_b + ((wn * 64 + bi * 16 + lrow) * STR + kk + lkof) * 2);
#pragma unroll
            for (int mi = 0; mi < 2; ++mi)
#pragma unroll
                for (int bi = 0; bi < 4; ++bi) {
                    mma16816(acc[mi][bi * 2 + 0], af[mi][0], af[mi][1], af[mi][2], af[mi][3],
                             bf[bi][0], bf[bi][2]);
                    mma16816(acc[mi][bi * 2 + 1], af[mi][0], af[mi][1], af[mi][2], af[mi][3],
                             bf[bi][1], bf[bi][3]);
                }

            // pass 1: Al x Bh (B fragments resident)
#pragma unroll
            for (int mi = 0; mi < 2; ++mi)
                ldsm_x4(af[mi][0], af[mi][1], af[mi][2], af[mi][3],
                        al_b + ((wm * 32 + mi * 16 + lrow) * STR + kk + lkof) * 2);
#pragma unroll
            for (int mi = 0; mi < 2; ++mi)
#pragma unroll
                for (int bi = 0; bi < 4; ++bi) {
                    mma16816(acc[mi][bi * 2 + 0], af[mi][0], af[mi][1], af[mi][2], af[mi][3],
                             bf[bi][0], bf[bi][2]);
                    mma16816(acc[mi][bi * 2 + 1], af[mi][0], af[mi][1], af[mi][2], af[mi][3],
                             bf[bi][1], bf[bi][3]);
                }

            // pass 2: Ah x Bl
#pragma unroll
            for (int mi = 0; mi < 2; ++mi)
                ldsm_x4(af[mi][0], af[mi][1], af[mi][2], af[mi][3],
                        ah_b + ((wm * 32 + mi * 16 + lrow) * STR + kk + lkof) * 2);
#pragma unroll
            for (int bi = 0; bi < 4; ++bi)
                ldsm_x4(bf[bi][0], bf[bi][1], bf[bi][2], bf[bi][3],
                        bl_b + ((wn * 64 + bi * 16 + lrow) * STR + kk + lkof) * 2);
#pragma unroll
            for (int mi = 0; mi < 2; ++mi)
#pragma unroll
                for (int bi = 0; bi < 4; ++bi) {
                    mma16816(acc[mi][bi * 2 + 0], af[mi][0], af[mi][1], af[mi][2], af[mi][3],
                             bf[bi][0], bf[bi][2]);
                    mma16816(acc[mi][bi * 2 + 1], af[mi][0], af[mi][1], af[mi][2], af[mi][3],
                             bf[bi][1], bf[bi][3]);
                }
        }
        __syncthreads();   // protect A tiles before next convert
    }

    // ---- epilogue: + bias, store t ----
    const int gid = lane >> 2;
    const int cid = (lane & 3) * 2;
#pragma unroll
    for (int mi = 0; mi < 2; ++mi) {
        int row0 = rowBase + wm * 32 + mi * 16 + gid;
#pragma unroll
        for (int ni = 0; ni < 8; ++ni) {
            int col = wn * 64 + ni * 8 + cid;
            float b0 = __ldg(bias + col), b1 = __ldg(bias + col + 1);
            if (row0 < E) {
                float2 o = {acc[mi][ni][0] + b0, acc[mi][ni][1] + b1};
                *(float2*)(g_t + (size_t)row0 * HID + col) = o;
            }
            if (row0 + 8 < E) {
                float2 o = {acc[mi][ni][2] + b0, acc[mi][ni][3] + b1};
                *(float2*)(g_t + (size_t)(row0 + 8) * HID + col) = o;
            }
        }
    }
}

// =====================================================================
// out[i] = t[i] + sum_k t[nbr[i][k]]   (L2-bound; unchanged)
// =====================================================================
__global__ __launch_bounds__(256)
void gather_sum_kernel(const int* __restrict__ nbr,
                       float* __restrict__ out,
                       int E) {
    int gtid = blockIdx.x * blockDim.x + threadIdx.x;
    int e    = gtid >> 5;
    int lane = threadIdx.x & 31;
    if (e >= E) return;

    const float4* T4 = (const float4*)g_t;

    int j = 0;
    if (lane < 16) j = nbr[e * 16 + lane];

    float4 acc = T4[e * 32 + lane];

    float4 v[16];
#pragma unroll
    for (int k = 0; k < 16; ++k) {
        int n = __shfl_sync(0xffffffffu, j, k);
        v[k] = T4[n * 32 + lane];
    }
#pragma unroll
    for (int k = 0; k < 16; ++k) {
        acc.x += v[k].x;
        acc.y += v[k].y;
        acc.z += v[k].z;
        acc.w += v[k].w;
    }
    ((float4*)out)[e * 32 + lane] = acc;
}

extern "C" void kernel_launch(void* const* d_in, const int* in_sizes, int n_in,
                              void* d_out, int out_size) {
    const float* X   = (const float*)d_in[0];   // edge_feats [E, 256]
    const int*   nbr = (const int*)  d_in[1];   // neighbors  [E, 16]
    const float* W   = (const float*)d_in[2];   // W          [256, 128]
    const float* b   = (const float*)d_in[3];   // b          [128]
    float* out = (float*)d_out;                 // [E, 128]

    int E = in_sizes[0] / IN_F;

    cudaFuncSetAttribute(gemm_mma_kernel,
                         cudaFuncAttributeMaxDynamicSharedMemorySize, SMEM_BYTES);

    wconv_kernel<<<(IN_F * HID + 255) / 256, 256>>>(W);

    int gblocks = (E + 127) / 128;
    gemm_mma_kernel<<<gblocks, 256, SMEM_BYTES>>>(X, b, E);

    long long threads = (long long)E * 32;      // one warp per edge
    int blocks2 = (int)((threads + 255) / 256);
    gather_sum_kernel<<<blocks2, 256>>>(nbr, out, E);
}

// round 7
// speedup vs baseline: 1.1638x; 1.0408x over previous
#include <cuda_runtime.h>
#include <cuda_bf16.h>
#include <cuda_fp16.h>
#include <cstdint>

#define E_MAX 100096
#define IN_F  256
#define HID   128

// scratch (device globals = allowed scratch)
__device__ float  g_t [(size_t)E_MAX * HID];    // fp32 t (self term)
__device__ __half g_th[(size_t)E_MAX * HID];    // fp16 t (gather term)
__device__ __nv_bfloat16 g_wt_hi[HID * IN_F];
__device__ __nv_bfloat16 g_wt_lo[HID * IN_F];

__device__ __forceinline__ uint32_t smem_u32(const void* p) {
    uint32_t a;
    asm("{ .reg .u64 t; cvta.to.shared.u64 t, %1; cvt.u32.u64 %0, t; }" : "=r"(a) : "l"(p));
    return a;
}
__device__ __forceinline__ void ldsm_x4(uint32_t& r0, uint32_t& r1, uint32_t& r2,
                                        uint32_t& r3, uint32_t addr) {
    asm volatile("ldmatrix.sync.aligned.m8n8.x4.shared.b16 {%0,%1,%2,%3}, [%4];"
                 : "=r"(r0), "=r"(r1), "=r"(r2), "=r"(r3) : "r"(addr));
}
__device__ __forceinline__ void mma16816(float* c, uint32_t a0, uint32_t a1,
                                         uint32_t a2, uint32_t a3,
                                         uint32_t b0, uint32_t b1) {
    asm volatile(
        "mma.sync.aligned.m16n8k16.row.col.f32.bf16.bf16.f32 "
        "{%0,%1,%2,%3}, {%4,%5,%6,%7}, {%8,%9}, {%0,%1,%2,%3};"
        : "+f"(c[0]), "+f"(c[1]), "+f"(c[2]), "+f"(c[3])
        : "r"(a0), "r"(a1), "r"(a2), "r"(a3), "r"(b0), "r"(b1));
}
__device__ __forceinline__ void cp_async16(uint32_t dst, const void* src) {
    asm volatile("cp.async.cg.shared.global [%0], [%1], 16;" :: "r"(dst), "l"(src));
}
#define CP_COMMIT() asm volatile("cp.async.commit_group;" ::: "memory")
#define CP_WAIT0()  asm volatile("cp.async.wait_group 0;" ::: "memory")

// =====================================================================
// W transpose + bf16 hi/lo split (one-shot tiny kernel)
// =====================================================================
__global__ void wconv_kernel(const float* __restrict__ W) {
    int i = blockIdx.x * 256 + threadIdx.x;
    if (i >= IN_F * HID) return;
    int k = i >> 7, n = i & 127;
    float v = W[i];
    __nv_bfloat16 h = __float2bfloat16(v);
    float lo = v - __bfloat162float(h);
    g_wt_hi[n * IN_F + k] = h;
    g_wt_lo[n * IN_F + k] = __float2bfloat16(lo);
}

// =====================================================================
// t = X @ W + b : bf16 3-term split on mma.sync, fp32 accum
// (R5 structure: cp.async double-buffered X fp32 + B bf16, single A tiles)
// Epilogue now also stores fp16 t for the gather kernel.
// =====================================================================
#define BK 32
#define STR 40
#define TILE_B (128 * STR * 2)

#define SM_XF 0
#define SM_AH 32768
#define SM_AL 43008
#define SM_B  53248
#define SMEM_BYTES (53248 + 40960)

__device__ __forceinline__ void prefetch_chunk(
    uint32_t smb, int buf,
    const float4* __restrict__ X4,
    const uint4* __restrict__ bh4, const uint4* __restrict__ bl4,
    int tid, int rowBase, int kc, int E)
{
    uint32_t xdst = smb + SM_XF + buf * 16384;
#pragma unroll
    for (int it = 0; it < 4; ++it) {
        int i = it * 256 + tid;
        int r = i >> 3, f = i & 7;
        int grow = rowBase + r;
        if (grow >= E) grow = E - 1;
        cp_async16(xdst + i * 16, X4 + grow * (IN_F / 4) + kc * 8 + f);
    }
    uint32_t bdst = smb + SM_B + buf * (2 * TILE_B);
#pragma unroll
    for (int it = 0; it < 2; ++it) {
        int i = it * 256 + tid;
        int n = i >> 2, q = i & 3;
        uint32_t off = (uint32_t)(n * STR + q * 8) * 2;
        cp_async16(bdst + off,          bh4 + n * 32 + kc * 4 + q);
        cp_async16(bdst + TILE_B + off, bl4 + n * 32 + kc * 4 + q);
    }
    CP_COMMIT();
}

__device__ __forceinline__ void convert_A(char* smem, int buf, int tid) {
    const float4* xf = (const float4*)(smem + SM_XF + buf * 16384);
    __nv_bfloat16* sAh = (__nv_bfloat16*)(smem + SM_AH);
    __nv_bfloat16* sAl = (__nv_bfloat16*)(smem + SM_AL);
#pragma unroll
    for (int it = 0; it < 4; ++it) {
        int i = it * 256 + tid;
        int r = i >> 3, f = i & 7;
        float4 v = xf[i];
        __nv_bfloat16 h0 = __float2bfloat16(v.x);
        __nv_bfloat16 h1 = __float2bfloat16(v.y);
        __nv_bfloat16 h2 = __float2bfloat16(v.z);
        __nv_bfloat16 h3 = __float2bfloat16(v.w);
        __nv_bfloat16 l0 = __float2bfloat16(v.x - __bfloat162float(h0));
        __nv_bfloat16 l1 = __float2bfloat16(v.y - __bfloat162float(h1));
        __nv_bfloat16 l2 = __float2bfloat16(v.z - __bfloat162float(h2));
        __nv_bfloat16 l3 = __float2bfloat16(v.w - __bfloat162float(h3));
        uint2 hp, lp;
        hp.x = ((uint32_t)__bfloat16_as_ushort(h1) << 16) | __bfloat16_as_ushort(h0);
        hp.y = ((uint32_t)__bfloat16_as_ushort(h3) << 16) | __bfloat16_as_ushort(h2);
        lp.x = ((uint32_t)__bfloat16_as_ushort(l1) << 16) | __bfloat16_as_ushort(l0);
        lp.y = ((uint32_t)__bfloat16_as_ushort(l3) << 16) | __bfloat16_as_ushort(l2);
        *(uint2*)(sAh + r * STR + f * 4) = hp;
        *(uint2*)(sAl + r * STR + f * 4) = lp;
    }
}

__global__ __launch_bounds__(256, 2)
void gemm_mma_kernel(const float* __restrict__ X,
                     const float* __restrict__ bias,
                     int E) {
    extern __shared__ char smem[];

    const int tid  = threadIdx.x;
    const int wid  = tid >> 5;
    const int lane = tid & 31;
    const int wm   = wid & 3;
    const int wn   = wid >> 2;
    const int rowBase = blockIdx.x * 128;

    float acc[2][8][4];
#pragma unroll
    for (int mi = 0; mi < 2; ++mi)
#pragma unroll
        for (int ni = 0; ni < 8; ++ni)
#pragma unroll
            for (int q = 0; q < 4; ++q) acc[mi][ni][q] = 0.f;

    const float4* X4  = (const float4*)X;
    const uint4*  bh4 = (const uint4*)g_wt_hi;
    const uint4*  bl4 = (const uint4*)g_wt_lo;

    const uint32_t smb = smem_u32(smem);

    const int lrow = (lane & 7) + ((lane >> 3) & 1) * 8;
    const int lkof = ((lane >> 4) & 1) * 8;

    prefetch_chunk(smb, 0, X4, bh4, bl4, tid, rowBase, 0, E);

    for (int kc = 0; kc < IN_F / BK; ++kc) {
        const int buf = kc & 1;

        CP_WAIT0();
        __syncthreads();

        convert_A(smem, buf, tid);

        if (kc + 1 < IN_F / BK)
            prefetch_chunk(smb, buf ^ 1, X4, bh4, bl4, tid, rowBase, kc + 1, E);

        __syncthreads();

        const uint32_t ah_b = smb + SM_AH;
        const uint32_t al_b = smb + SM_AL;
        const uint32_t bh_b = smb + SM_B + (uint32_t)buf * (2 * TILE_B);
        const uint32_t bl_b = bh_b + TILE_B;

#pragma unroll
        for (int ks = 0; ks < 2; ++ks) {
            const int kk = ks * 16;
            uint32_t af[2][4], bf[4][4];

            // pass 0: Ah x Bh
#pragma unroll
            for (int mi = 0; mi < 2; ++mi)
                ldsm_x4(af[mi][0], af[mi][1], af[mi][2], af[mi][3],
                        ah_b + ((wm * 32 + mi * 16 + lrow) * STR + kk + lkof) * 2);
#pragma unroll
            for (int bi = 0; bi < 4; ++bi)
                ldsm_x4(bf[bi][0], bf[bi][1], bf[bi][2], bf[bi][3],
                        bh_b + ((wn * 64 + bi * 16 + lrow) * STR + kk + lkof) * 2);
#pragma unroll
            for (int mi = 0; mi < 2; ++mi)
#pragma unroll
                for (int bi = 0; bi < 4; ++bi) {
                    mma16816(acc[mi][bi * 2 + 0], af[mi][0], af[mi][1], af[mi][2], af[mi][3],
                             bf[bi][0], bf[bi][2]);
                    mma16816(acc[mi][bi * 2 + 1], af[mi][0], af[mi][1], af[mi][2], af[mi][3],
                             bf[bi][1], bf[bi][3]);
                }

            // pass 1: Al x Bh
#pragma unroll
            for (int mi = 0; mi < 2; ++mi)
                ldsm_x4(af[mi][0], af[mi][1], af[mi][2], af[mi][3],
                        al_b + ((wm * 32 + mi * 16 + lrow) * STR + kk + lkof) * 2);
#pragma unroll
            for (int mi = 0; mi < 2; ++mi)
#pragma unroll
                for (int bi = 0; bi < 4; ++bi) {
                    mma16816(acc[mi][bi * 2 + 0], af[mi][0], af[mi][1], af[mi][2], af[mi][3],
                             bf[bi][0], bf[bi][2]);
                    mma16816(acc[mi][bi * 2 + 1], af[mi][0], af[mi][1], af[mi][2], af[mi][3],
                             bf[bi][1], bf[bi][3]);
                }

            // pass 2: Ah x Bl
#pragma unroll
            for (int mi = 0; mi < 2; ++mi)
                ldsm_x4(af[mi][0], af[mi][1], af[mi][2], af[mi][3],
                        ah_b + ((wm * 32 + mi * 16 + lrow) * STR + kk + lkof) * 2);
#pragma unroll
            for (int bi = 0; bi < 4; ++bi)
                ldsm_x4(bf[bi][0], bf[bi][1], bf[bi][2], bf[bi][3],
                        bl_b + ((wn * 64 + bi * 16 + lrow) * STR + kk + lkof) * 2);
#pragma unroll
            for (int mi = 0; mi < 2; ++mi)
#pragma unroll
                for (int bi = 0; bi < 4; ++bi) {
                    mma16816(acc[mi][bi * 2 + 0], af[mi][0], af[mi][1], af[mi][2], af[mi][3],
                             bf[bi][0], bf[bi][2]);
                    mma16816(acc[mi][bi * 2 + 1], af[mi][0], af[mi][1], af[mi][2], af[mi][3],
                             bf[bi][1], bf[bi][3]);
                }
        }
        __syncthreads();
    }

    // ---- epilogue: + bias, store fp32 t AND fp16 t ----
    const int gid = lane >> 2;
    const int cid = (lane & 3) * 2;
#pragma unroll
    for (int mi = 0; mi < 2; ++mi) {
        int row0 = rowBase + wm * 32 + mi * 16 + gid;
#pragma unroll
        for (int ni = 0; ni < 8; ++ni) {
            int col = wn * 64 + ni * 8 + cid;
            float b0 = __ldg(bias + col), b1 = __ldg(bias + col + 1);
            if (row0 < E) {
                float2 o = {acc[mi][ni][0] + b0, acc[mi][ni][1] + b1};
                *(float2*)(g_t + (size_t)row0 * HID + col) = o;
                *(__half2*)(g_th + (size_t)row0 * HID + col) = __floats2half2_rn(o.x, o.y);
            }
            if (row0 + 8 < E) {
                float2 o = {acc[mi][ni][2] + b0, acc[mi][ni][3] + b1};
                *(float2*)(g_t + (size_t)(row0 + 8) * HID + col) = o;
                *(__half2*)(g_th + (size_t)(row0 + 8) * HID + col) = __floats2half2_rn(o.x, o.y);
            }
        }
    }
}

// =====================================================================
// out[i] = t_fp32[i] + sum_k fp16(t[nbr[i][k]])
// warp/edge; gathered rows are fp16 (256B) -> half the L2 traffic.
// =====================================================================
__global__ __launch_bounds__(256)
void gather_sum_kernel(const int* __restrict__ nbr,
                       float* __restrict__ out,
                       int E) {
    int gtid = blockIdx.x * blockDim.x + threadIdx.x;
    int e    = gtid >> 5;
    int lane = threadIdx.x & 31;
    if (e >= E) return;

    const float4* T4 = (const float4*)g_t;
    const uint2*  H2 = (const uint2*)g_th;    // 4 halves per uint2; 32 per row

    int j = 0;
    if (lane < 16) j = nbr[e * 16 + lane];

    float4 acc = T4[e * 32 + lane];           // self (fp32), cols [lane*4, lane*4+4)

    uint2 v[16];
#pragma unroll
    for (int k = 0; k < 16; ++k) {
        int n = __shfl_sync(0xffffffffu, j, k);
        v[k] = H2[n * 32 + lane];
    }
#pragma unroll
    for (int k = 0; k < 16; ++k) {
        float2 a = __half22float2(*(const __half2*)&v[k].x);
        float2 b = __half22float2(*(const __half2*)&v[k].y);
        acc.x += a.x;
        acc.y += a.y;
        acc.z += b.x;
        acc.w += b.y;
    }
    ((float4*)out)[e * 32 + lane] = acc;
}

extern "C" void kernel_launch(void* const* d_in, const int* in_sizes, int n_in,
                              void* d_out, int out_size) {
    const float* X   = (const float*)d_in[0];   // edge_feats [E, 256]
    const int*   nbr = (const int*)  d_in[1];   // neighbors  [E, 16]
    const float* W   = (const float*)d_in[2];   // W          [256, 128]
    const float* b   = (const float*)d_in[3];   // b          [128]
    float* out = (float*)d_out;                 // [E, 128]

    int E = in_sizes[0] / IN_F;

    cudaFuncSetAttribute(gemm_mma_kernel,
                         cudaFuncAttributeMaxDynamicSharedMemorySize, SMEM_BYTES);

    wconv_kernel<<<(IN_F * HID + 255) / 256, 256>>>(W);

    int gblocks = (E + 127) / 128;
    gemm_mma_kernel<<<gblocks, 256, SMEM_BYTES>>>(X, b, E);

    long long threads = (long long)E * 32;      // one warp per edge
    int blocks2 = (int)((threads + 255) / 256);
    gather_sum_kernel<<<blocks2, 256>>>(nbr, out, E);
}

// round 8
// speedup vs baseline: 1.5188x; 1.3050x over previous
#include <cuda_runtime.h>
#include <cuda_fp16.h>
#include <cstdint>

#define E_MAX 100096
#define IN_F  256
#define HID   128

// scratch (device globals = allowed scratch)
__device__ __half g_th[(size_t)E_MAX * HID];    // fp16 t (self + gather)
__device__ __half g_wh[HID * IN_F];             // W transposed [n][k], fp16

__device__ __forceinline__ uint32_t smem_u32(const void* p) {
    uint32_t a;
    asm("{ .reg .u64 t; cvta.to.shared.u64 t, %1; cvt.u32.u64 %0, t; }" : "=r"(a) : "l"(p));
    return a;
}
__device__ __forceinline__ void ldsm_x4(uint32_t& r0, uint32_t& r1, uint32_t& r2,
                                        uint32_t& r3, uint32_t addr) {
    asm volatile("ldmatrix.sync.aligned.m8n8.x4.shared.b16 {%0,%1,%2,%3}, [%4];"
                 : "=r"(r0), "=r"(r1), "=r"(r2), "=r"(r3) : "r"(addr));
}
__device__ __forceinline__ void mma16816(float* c, uint32_t a0, uint32_t a1,
                                         uint32_t a2, uint32_t a3,
                                         uint32_t b0, uint32_t b1) {
    asm volatile(
        "mma.sync.aligned.m16n8k16.row.col.f32.f16.f16.f32 "
        "{%0,%1,%2,%3}, {%4,%5,%6,%7}, {%8,%9}, {%0,%1,%2,%3};"
        : "+f"(c[0]), "+f"(c[1]), "+f"(c[2]), "+f"(c[3])
        : "r"(a0), "r"(a1), "r"(a2), "r"(a3), "r"(b0), "r"(b1));
}
__device__ __forceinline__ void cp_async16(uint32_t dst, const void* src) {
    asm volatile("cp.async.cg.shared.global [%0], [%1], 16;" :: "r"(dst), "l"(src));
}
#define CP_COMMIT() asm volatile("cp.async.commit_group;" ::: "memory")
#define CP_WAIT0()  asm volatile("cp.async.wait_group 0;" ::: "memory")

// =====================================================================
// W transpose -> fp16 (one-shot tiny kernel)
// =====================================================================
__global__ void wconv_kernel(const float* __restrict__ W) {
    int i = blockIdx.x * 256 + threadIdx.x;
    if (i >= IN_F * HID) return;
    int k = i >> 7, n = i & 127;
    g_wh[n * IN_F + k] = __float2half_rn(W[i]);
}

// =====================================================================
// t = X @ Wh + b : fp16 2-term split (Xh*Wh + Xl*Wh), fp32 accum
// CTA = 128x128, 8 warps (4m x 2n), BK=32, cp.async double-buffered.
// =====================================================================
#define BK 32
#define STR 40                       // smem row stride (halves): 80 B
#define TILE_B (128 * STR * 2)       // 10240 B per fp16 tile

#define SM_XF 0                      // X fp32 staging: 2 x 16384
#define SM_AH 32768                  // A hi fp16 tile (single)
#define SM_AL 43008                  // A lo fp16 tile (single)
#define SM_B  53248                  // B hi tiles: 2 x 10240 (double-buffered)
#define SMEM_BYTES (53248 + 20480)   // 73728

__device__ __forceinline__ void prefetch_chunk(
    uint32_t smb, int buf,
    const float4* __restrict__ X4,
    const uint4* __restrict__ bh4,
    int tid, int rowBase, int kc, int E)
{
    uint32_t xdst = smb + SM_XF + buf * 16384;
#pragma unroll
    for (int it = 0; it < 4; ++it) {
        int i = it * 256 + tid;          // 1024 float4
        int r = i >> 3, f = i & 7;
        int grow = rowBase + r;
        if (grow >= E) grow = E - 1;
        cp_async16(xdst + i * 16, X4 + grow * (IN_F / 4) + kc * 8 + f);
    }
    uint32_t bdst = smb + SM_B + buf * TILE_B;
#pragma unroll
    for (int it = 0; it < 2; ++it) {
        int i = it * 256 + tid;          // 512 uint4
        int n = i >> 2, q = i & 3;
        uint32_t off = (uint32_t)(n * STR + q * 8) * 2;    // 16B-aligned
        cp_async16(bdst + off, bh4 + n * 32 + kc * 4 + q);
    }
    CP_COMMIT();
}

__device__ __forceinline__ void convert_A(char* smem, int buf, int tid) {
    const float4* xf = (const float4*)(smem + SM_XF + buf * 16384);
    __half* sAh = (__half*)(smem + SM_AH);
    __half* sAl = (__half*)(smem + SM_AL);
#pragma unroll
    for (int it = 0; it < 4; ++it) {
        int i = it * 256 + tid;
        int r = i >> 3, f = i & 7;
        float4 v = xf[i];
        __half h0 = __float2half_rn(v.x);
        __half h1 = __float2half_rn(v.y);
        __half h2 = __float2half_rn(v.z);
        __half h3 = __float2half_rn(v.w);
        __half l0 = __float2half_rn(v.x - __half2float(h0));
        __half l1 = __float2half_rn(v.y - __half2float(h1));
        __half l2 = __float2half_rn(v.z - __half2float(h2));
        __half l3 = __float2half_rn(v.w - __half2float(h3));
        uint2 hp, lp;
        hp.x = ((uint32_t)__half_as_ushort(h1) << 16) | __half_as_ushort(h0);
        hp.y = ((uint32_t)__half_as_ushort(h3) << 16) | __half_as_ushort(h2);
        lp.x = ((uint32_t)__half_as_ushort(l1) << 16) | __half_as_ushort(l0);
        lp.y = ((uint32_t)__half_as_ushort(l3) << 16) | __half_as_ushort(l2);
        *(uint2*)(sAh + r * STR + f * 4) = hp;
        *(uint2*)(sAl + r * STR + f * 4) = lp;
    }
}

__global__ __launch_bounds__(256, 2)
void gemm_mma_kernel(const float* __restrict__ X,
                     const float* __restrict__ bias,
                     int E) {
    extern __shared__ char smem[];

    const int tid  = threadIdx.x;
    const int wid  = tid >> 5;
    const int lane = tid & 31;
    const int wm   = wid & 3;
    const int wn   = wid >> 2;
    const int rowBase = blockIdx.x * 128;

    float acc[2][8][4];
#pragma unroll
    for (int mi = 0; mi < 2; ++mi)
#pragma unroll
        for (int ni = 0; ni < 8; ++ni)
#pragma unroll
            for (int q = 0; q < 4; ++q) acc[mi][ni][q] = 0.f;

    const float4* X4  = (const float4*)X;
    const uint4*  bh4 = (const uint4*)g_wh;

    const uint32_t smb = smem_u32(smem);

    const int lrow = (lane & 7) + ((lane >> 3) & 1) * 8;
    const int lkof = ((lane >> 4) & 1) * 8;

    prefetch_chunk(smb, 0, X4, bh4, tid, rowBase, 0, E);

    for (int kc = 0; kc < IN_F / BK; ++kc) {
        const int buf = kc & 1;

        CP_WAIT0();
        __syncthreads();

        convert_A(smem, buf, tid);

        if (kc + 1 < IN_F / BK)
            prefetch_chunk(smb, buf ^ 1, X4, bh4, tid, rowBase, kc + 1, E);

        __syncthreads();

        const uint32_t ah_b = smb + SM_AH;
        const uint32_t al_b = smb + SM_AL;
        const uint32_t bh_b = smb + SM_B + (uint32_t)buf * TILE_B;

#pragma unroll
        for (int ks = 0; ks < 2; ++ks) {
            const int kk = ks * 16;
            uint32_t af[2][4], bf[4][4];

            // pass 0: Ah x Bh
#pragma unroll
            for (int mi = 0; mi < 2; ++mi)
                ldsm_x4(af[mi][0], af[mi][1], af[mi][2], af[mi][3],
                        ah_b + ((wm * 32 + mi * 16 + lrow) * STR + kk + lkof) * 2);
#pragma unroll
            for (int bi = 0; bi < 4; ++bi)
                ldsm_x4(bf[bi][0], bf[bi][1], bf[bi][2], bf[bi][3],
                        bh_b + ((wn * 64 + bi * 16 + lrow) * STR + kk + lkof) * 2);
#pragma unroll
            for (int mi = 0; mi < 2; ++mi)
#pragma unroll
                for (int bi = 0; bi < 4; ++bi) {
                    mma16816(acc[mi][bi * 2 + 0], af[mi][0], af[mi][1], af[mi][2], af[mi][3],
                             bf[bi][0], bf[bi][2]);
                    mma16816(acc[mi][bi * 2 + 1], af[mi][0], af[mi][1], af[mi][2], af[mi][3],
                             bf[bi][1], bf[bi][3]);
                }

            // pass 1: Al x Bh (B fragments resident)
#pragma unroll
            for (int mi = 0; mi < 2; ++mi)
                ldsm_x4(af[mi][0], af[mi][1], af[mi][2], af[mi][3],
                        al_b + ((wm * 32 + mi * 16 + lrow) * STR + kk + lkof) * 2);
#pragma unroll
            for (int mi = 0; mi < 2; ++mi)
#pragma unroll
                for (int bi = 0; bi < 4; ++bi) {
                    mma16816(acc[mi][bi * 2 + 0], af[mi][0], af[mi][1], af[mi][2], af[mi][3],
                             bf[bi][0], bf[bi][2]);
                    mma16816(acc[mi][bi * 2 + 1], af[mi][0], af[mi][1], af[mi][2], af[mi][3],
                             bf[bi][1], bf[bi][3]);
                }
        }
        __syncthreads();
    }

    // ---- epilogue: + bias, store fp16 t only ----
    const int gid = lane >> 2;
    const int cid = (lane & 3) * 2;
#pragma unroll
    for (int mi = 0; mi < 2; ++mi) {
        int row0 = rowBase + wm * 32 + mi * 16 + gid;
#pragma unroll
        for (int ni = 0; ni < 8; ++ni) {
            int col = wn * 64 + ni * 8 + cid;
            float b0 = __ldg(bias + col), b1 = __ldg(bias + col + 1);
            if (row0 < E) {
                *(__half2*)(g_th + (size_t)row0 * HID + col) =
                    __floats2half2_rn(acc[mi][ni][0] + b0, acc[mi][ni][1] + b1);
            }
            if (row0 + 8 < E) {
                *(__half2*)(g_th + (size_t)(row0 + 8) * HID + col) =
                    __floats2half2_rn(acc[mi][ni][2] + b0, acc[mi][ni][3] + b1);
            }
        }
    }
}

// =====================================================================
// out[i] = fp16(t[i]) + sum_k fp16(t[nbr[i][k]])  (fp32 accumulate/write)
// warp/edge; all rows fp16 (256B) -> minimal L2 traffic.
// =====================================================================
__global__ __launch_bounds__(256)
void gather_sum_kernel(const int* __restrict__ nbr,
                       float* __restrict__ out,
                       int E) {
    int gtid = blockIdx.x * blockDim.x + threadIdx.x;
    int e    = gtid >> 5;
    int lane = threadIdx.x & 31;
    if (e >= E) return;

    const uint2* H2 = (const uint2*)g_th;    // 4 halves per uint2; 32 per row

    int j = 0;
    if (lane < 16) j = nbr[e * 16 + lane];

    uint2 s = H2[e * 32 + lane];             // self
    float2 sa = __half22float2(*(const __half2*)&s.x);
    float2 sb = __half22float2(*(const __half2*)&s.y);
    float4 acc = {sa.x, sa.y, sb.x, sb.y};

    uint2 v[16];
#pragma unroll
    for (int k = 0; k < 16; ++k) {
        int n = __shfl_sync(0xffffffffu, j, k);
        v[k] = H2[n * 32 + lane];
    }
#pragma unroll
    for (int k = 0; k < 16; ++k) {
        float2 a = __half22float2(*(const __half2*)&v[k].x);
        float2 b = __half22float2(*(const __half2*)&v[k].y);
        acc.x += a.x;
        acc.y += a.y;
        acc.z += b.x;
        acc.w += b.y;
    }
    ((float4*)out)[e * 32 + lane] = acc;
}

extern "C" void kernel_launch(void* const* d_in, const int* in_sizes, int n_in,
                              void* d_out, int out_size) {
    const float* X   = (const float*)d_in[0];   // edge_feats [E, 256]
    const int*   nbr = (const int*)  d_in[1];   // neighbors  [E, 16]
    const float* W   = (const float*)d_in[2];   // W          [256, 128]
    const float* b   = (const float*)d_in[3];   // b          [128]
    float* out = (float*)d_out;                 // [E, 128]

    int E = in_sizes[0] / IN_F;

    cudaFuncSetAttribute(gemm_mma_kernel,
                         cudaFuncAttributeMaxDynamicSharedMemorySize, SMEM_BYTES);

    wconv_kernel<<<(IN_F * HID + 255) / 256, 256>>>(W);

    int gblocks = (E + 127) / 128;
    gemm_mma_kernel<<<gblocks, 256, SMEM_BYTES>>>(X, b, E);

    long long threads = (long long)E * 32;      // one warp per edge
    int blocks2 = (int)((threads + 255) / 256);
    gather_sum_kernel<<<blocks2, 256>>>(nbr, out, E);
}

// round 9
// speedup vs baseline: 1.7564x; 1.1564x over previous
#include <cuda_runtime.h>
#include <cuda_fp16.h>
#include <cstdint>

#define E_MAX 100096
#define IN_F  256
#define HID   128

// scratch (device globals = allowed scratch)
__device__ __half g_th[(size_t)E_MAX * HID];    // fp16 t (self + gather)
__device__ __half g_wh[HID * IN_F];             // W transposed [n][k], fp16

__device__ __forceinline__ uint32_t smem_u32(const void* p) {
    uint32_t a;
    asm("{ .reg .u64 t; cvta.to.shared.u64 t, %1; cvt.u32.u64 %0, t; }" : "=r"(a) : "l"(p));
    return a;
}
__device__ __forceinline__ void ldsm_x4(uint32_t& r0, uint32_t& r1, uint32_t& r2,
                                        uint32_t& r3, uint32_t addr) {
    asm volatile("ldmatrix.sync.aligned.m8n8.x4.shared.b16 {%0,%1,%2,%3}, [%4];"
                 : "=r"(r0), "=r"(r1), "=r"(r2), "=r"(r3) : "r"(addr));
}
__device__ __forceinline__ void mma16816(float* c, uint32_t a0, uint32_t a1,
                                         uint32_t a2, uint32_t a3,
                                         uint32_t b0, uint32_t b1) {
    asm volatile(
        "mma.sync.aligned.m16n8k16.row.col.f32.f16.f16.f32 "
        "{%0,%1,%2,%3}, {%4,%5,%6,%7}, {%8,%9}, {%0,%1,%2,%3};"
        : "+f"(c[0]), "+f"(c[1]), "+f"(c[2]), "+f"(c[3])
        : "r"(a0), "r"(a1), "r"(a2), "r"(a3), "r"(b0), "r"(b1));
}
__device__ __forceinline__ void cp_async16(uint32_t dst, const void* src) {
    asm volatile("cp.async.cg.shared.global [%0], [%1], 16;" :: "r"(dst), "l"(src));
}
#define CP_COMMIT() asm volatile("cp.async.commit_group;" ::: "memory")
#define CP_WAIT0()  asm volatile("cp.async.wait_group 0;" ::: "memory")

// =====================================================================
// W transpose -> fp16 (one-shot tiny kernel)
// =====================================================================
__global__ void wconv_kernel(const float* __restrict__ W) {
    int i = blockIdx.x * 256 + threadIdx.x;
    if (i >= IN_F * HID) return;
    int k = i >> 7, n = i & 127;
    g_wh[n * IN_F + k] = __float2half_rn(W[i]);
}

// =====================================================================
// t = Xh @ Wh + b : single-pass fp16 HMMA, fp32 accum
// CTA = 128x128, 8 warps (4m x 2n), BK=32, cp.async double-buffered.
// =====================================================================
#define BK 32
#define STR 40                       // smem row stride (halves): 80 B
#define TILE_B (128 * STR * 2)       // 10240 B per fp16 tile

#define SM_XF 0                      // X fp32 staging: 2 x 16384
#define SM_AH 32768                  // A fp16 tile (single)
#define SM_B  43008                  // B tiles: 2 x 10240 (double-buffered)
#define SMEM_BYTES (43008 + 20480)   // 63488

__device__ __forceinline__ void prefetch_chunk(
    uint32_t smb, int buf,
    const float4* __restrict__ X4,
    const uint4* __restrict__ bh4,
    int tid, int rowBase, int kc, int E)
{
    uint32_t xdst = smb + SM_XF + buf * 16384;
#pragma unroll
    for (int it = 0; it < 4; ++it) {
        int i = it * 256 + tid;          // 1024 float4
        int r = i >> 3, f = i & 7;
        int grow = rowBase + r;
        if (grow >= E) grow = E - 1;
        cp_async16(xdst + i * 16, X4 + grow * (IN_F / 4) + kc * 8 + f);
    }
    uint32_t bdst = smb + SM_B + buf * TILE_B;
#pragma unroll
    for (int it = 0; it < 2; ++it) {
        int i = it * 256 + tid;          // 512 uint4
        int n = i >> 2, q = i & 3;
        uint32_t off = (uint32_t)(n * STR + q * 8) * 2;    // 16B-aligned
        cp_async16(bdst + off, bh4 + n * 32 + kc * 4 + q);
    }
    CP_COMMIT();
}

__device__ __forceinline__ void convert_A(char* smem, int buf, int tid) {
    const float4* xf = (const float4*)(smem + SM_XF + buf * 16384);
    __half* sAh = (__half*)(smem + SM_AH);
#pragma unroll
    for (int it = 0; it < 4; ++it) {
        int i = it * 256 + tid;
        int r = i >> 3, f = i & 7;
        float4 v = xf[i];
        uint2 hp;
        hp.x = ((uint32_t)__half_as_ushort(__float2half_rn(v.y)) << 16)
             |  __half_as_ushort(__float2half_rn(v.x));
        hp.y = ((uint32_t)__half_as_ushort(__float2half_rn(v.w)) << 16)
             |  __half_as_ushort(__float2half_rn(v.z));
        *(uint2*)(sAh + r * STR + f * 4) = hp;
    }
}

__global__ __launch_bounds__(256, 2)
void gemm_mma_kernel(const float* __restrict__ X,
                     const float* __restrict__ bias,
                     int E) {
    extern __shared__ char smem[];

    const int tid  = threadIdx.x;
    const int wid  = tid >> 5;
    const int lane = tid & 31;
    const int wm   = wid & 3;
    const int wn   = wid >> 2;
    const int rowBase = blockIdx.x * 128;

    float acc[2][8][4];
#pragma unroll
    for (int mi = 0; mi < 2; ++mi)
#pragma unroll
        for (int ni = 0; ni < 8; ++ni)
#pragma unroll
            for (int q = 0; q < 4; ++q) acc[mi][ni][q] = 0.f;

    const float4* X4  = (const float4*)X;
    const uint4*  bh4 = (const uint4*)g_wh;

    const uint32_t smb = smem_u32(smem);

    const int lrow = (lane & 7) + ((lane >> 3) & 1) * 8;
    const int lkof = ((lane >> 4) & 1) * 8;

    prefetch_chunk(smb, 0, X4, bh4, tid, rowBase, 0, E);

    for (int kc = 0; kc < IN_F / BK; ++kc) {
        const int buf = kc & 1;

        CP_WAIT0();
        __syncthreads();

        convert_A(smem, buf, tid);

        if (kc + 1 < IN_F / BK)
            prefetch_chunk(smb, buf ^ 1, X4, bh4, tid, rowBase, kc + 1, E);

        __syncthreads();

        const uint32_t ah_b = smb + SM_AH;
        const uint32_t bh_b = smb + SM_B + (uint32_t)buf * TILE_B;

#pragma unroll
        for (int ks = 0; ks < 2; ++ks) {
            const int kk = ks * 16;
            uint32_t af[2][4], bf[4][4];

#pragma unroll
            for (int mi = 0; mi < 2; ++mi)
                ldsm_x4(af[mi][0], af[mi][1], af[mi][2], af[mi][3],
                        ah_b + ((wm * 32 + mi * 16 + lrow) * STR + kk + lkof) * 2);
#pragma unroll
            for (int bi = 0; bi < 4; ++bi)
                ldsm_x4(bf[bi][0], bf[bi][1], bf[bi][2], bf[bi][3],
                        bh_b + ((wn * 64 + bi * 16 + lrow) * STR + kk + lkof) * 2);
#pragma unroll
            for (int mi = 0; mi < 2; ++mi)
#pragma unroll
                for (int bi = 0; bi < 4; ++bi) {
                    mma16816(acc[mi][bi * 2 + 0], af[mi][0], af[mi][1], af[mi][2], af[mi][3],
                             bf[bi][0], bf[bi][2]);
                    mma16816(acc[mi][bi * 2 + 1], af[mi][0], af[mi][1], af[mi][2], af[mi][3],
                             bf[bi][1], bf[bi][3]);
                }
        }
        __syncthreads();
    }

    // ---- epilogue: + bias, store fp16 t ----
    const int gid = lane >> 2;
    const int cid = (lane & 3) * 2;
#pragma unroll
    for (int mi = 0; mi < 2; ++mi) {
        int row0 = rowBase + wm * 32 + mi * 16 + gid;
#pragma unroll
        for (int ni = 0; ni < 8; ++ni) {
            int col = wn * 64 + ni * 8 + cid;
            float b0 = __ldg(bias + col), b1 = __ldg(bias + col + 1);
            if (row0 < E) {
                *(__half2*)(g_th + (size_t)row0 * HID + col) =
                    __floats2half2_rn(acc[mi][ni][0] + b0, acc[mi][ni][1] + b1);
            }
            if (row0 + 8 < E) {
                *(__half2*)(g_th + (size_t)(row0 + 8) * HID + col) =
                    __floats2half2_rn(acc[mi][ni][2] + b0, acc[mi][ni][3] + b1);
            }
        }
    }
}

// =====================================================================
// out[i] = fp16(t[i]) + sum_k fp16(t[nbr[i][k]])  (fp32 accumulate/write)
// =====================================================================
__global__ __launch_bounds__(256)
void gather_sum_kernel(const int* __restrict__ nbr,
                       float* __restrict__ out,
                       int E) {
    int gtid = blockIdx.x * blockDim.x + threadIdx.x;
    int e    = gtid >> 5;
    int lane = threadIdx.x & 31;
    if (e >= E) return;

    const uint2* H2 = (const uint2*)g_th;    // 4 halves per uint2; 32 per row

    int j = 0;
    if (lane < 16) j = nbr[e * 16 + lane];

    uint2 s = H2[e * 32 + lane];             // self
    float2 sa = __half22float2(*(const __half2*)&s.x);
    float2 sb = __half22float2(*(const __half2*)&s.y);
    float4 acc = {sa.x, sa.y, sb.x, sb.y};

    uint2 v[16];
#pragma unroll
    for (int k = 0; k < 16; ++k) {
        int n = __shfl_sync(0xffffffffu, j, k);
        v[k] = H2[n * 32 + lane];
    }
#pragma unroll
    for (int k = 0; k < 16; ++k) {
        float2 a = __half22float2(*(const __half2*)&v[k].x);
        float2 b = __half22float2(*(const __half2*)&v[k].y);
        acc.x += a.x;
        acc.y += a.y;
        acc.z += b.x;
        acc.w += b.y;
    }
    ((float4*)out)[e * 32 + lane] = acc;
}

extern "C" void kernel_launch(void* const* d_in, const int* in_sizes, int n_in,
                              void* d_out, int out_size) {
    const float* X   = (const float*)d_in[0];   // edge_feats [E, 256]
    const int*   nbr = (const int*)  d_in[1];   // neighbors  [E, 16]
    const float* W   = (const float*)d_in[2];   // W          [256, 128]
    const float* b   = (const float*)d_in[3];   // b          [128]
    float* out = (float*)d_out;                 // [E, 128]

    int E = in_sizes[0] / IN_F;

    cudaFuncSetAttribute(gemm_mma_kernel,
                         cudaFuncAttributeMaxDynamicSharedMemorySize, SMEM_BYTES);

    wconv_kernel<<<(IN_F * HID + 255) / 256, 256>>>(W);

    int gblocks = (E + 127) / 128;
    gemm_mma_kernel<<<gblocks, 256, SMEM_BYTES>>>(X, b, E);

    long long threads = (long long)E * 32;      // one warp per edge
    int blocks2 = (int)((threads + 255) / 256);
    gather_sum_kernel<<<blocks2, 256>>>(nbr, out, E);
}